// round 1
// baseline (speedup 1.0000x reference)
#include <cuda_runtime.h>
#include <stdint.h>

// JAX threefry semantics switch:
//  1 = jax_threefry_partitionable=True (default since jax 0.4.36)
//  0 = legacy ("original") split/random_bits
#ifndef JAX_PARTITIONABLE
#define JAX_PARTITIONABLE 1
#endif

#define VIS_WORDS 640              // covers n_faces up to 20480 bits
#define SEQ_CAP   64               // L+1 = 64 for this problem
#define SMEM_BYTES ((VIS_WORDS * 32 + SEQ_CAP * 32) * 4)

struct U2 { uint32_t x, y; };

// Threefry-2x32, 20 rounds — exact JAX/Random123 schedule.
__device__ __forceinline__ U2 tf(uint32_t k0, uint32_t k1, uint32_t x0, uint32_t x1) {
    uint32_t ks2 = k0 ^ k1 ^ 0x1BD11BDAu;
    x0 += k0; x1 += k1;
#define TF_R(r) { x0 += x1; x1 = __funnelshift_l(x1, x1, (r)); x1 ^= x0; }
    TF_R(13) TF_R(15) TF_R(26) TF_R(6)
    x0 += k1;  x1 += ks2 + 1u;
    TF_R(17) TF_R(29) TF_R(16) TF_R(24)
    x0 += ks2; x1 += k0 + 2u;
    TF_R(13) TF_R(15) TF_R(26) TF_R(6)
    x0 += k0;  x1 += k1 + 3u;
    TF_R(17) TF_R(29) TF_R(16) TF_R(24)
    x0 += k1;  x1 += ks2 + 4u;
    TF_R(13) TF_R(15) TF_R(26) TF_R(6)
    x0 += ks2; x1 += k0 + 5u;
#undef TF_R
    U2 o; o.x = x0; o.y = x1; return o;
}

// random_bits(key, 32, ())
__device__ __forceinline__ uint32_t tf_bits(U2 k) {
    U2 o = tf(k.x, k.y, 0u, 0u);
#if JAX_PARTITIONABLE
    return o.x ^ o.y;
#else
    return o.x;
#endif
}

// split(key, 2)
__device__ __forceinline__ void split2(U2 k, U2* a, U2* b) {
#if JAX_PARTITIONABLE
    *a = tf(k.x, k.y, 0u, 0u); *b = tf(k.x, k.y, 0u, 1u);
#else
    *a = tf(k.x, k.y, 0u, 2u); *b = tf(k.x, k.y, 1u, 3u);
#endif
}

// split(key, 4) — elements 0,1 and 2,3 separately (2,3 only needed on backtrack)
__device__ __forceinline__ void split4_01(U2 k, U2* a, U2* b) {
#if JAX_PARTITIONABLE
    *a = tf(k.x, k.y, 0u, 0u); *b = tf(k.x, k.y, 0u, 1u);
#else
    *a = tf(k.x, k.y, 0u, 4u); *b = tf(k.x, k.y, 1u, 5u);
#endif
}
__device__ __forceinline__ void split4_23(U2 k, U2* c, U2* d) {
#if JAX_PARTITIONABLE
    *c = tf(k.x, k.y, 0u, 2u); *d = tf(k.x, k.y, 0u, 3u);
#else
    *c = tf(k.x, k.y, 2u, 6u); *d = tf(k.x, k.y, 3u, 7u);
#endif
}

// randint(key, (), 0, span) for span >= 1 (JAX double-width unbiasing)
__device__ __forceinline__ uint32_t jrandint(U2 k, uint32_t span) {
    U2 ka, kb; split2(k, &ka, &kb);
    uint32_t h = tf_bits(ka), l = tf_bits(kb);
    uint32_t m = 65536u % span; m = (m * m) % span;
    return ((h % span) * m + (l % span)) % span;
}

__global__ void __launch_bounds__(32, 1)
walk_gather_kernel(const float* __restrict__ xyz,
                   const int*   __restrict__ nbrs,
                   const int*   __restrict__ centers,
                   const int*   __restrict__ pN,
                   float*       __restrict__ out,
                   int xyz_total, int walks, int L)
{
    extern __shared__ uint32_t sm[];
    uint32_t* vis = sm;                                 // [VIS_WORDS][32] lane-interleaved
    int*      seq = (int*)(sm + VIS_WORDS * 32);        // [SEQ_CAP][32]

    const int lane = threadIdx.x;
    const int wid  = blockIdx.x * 32 + lane;            // walk id = b*G + g
    const int N    = *pN;
    const int B    = xyz_total / (3 * N);
    const int G    = walks / B;

    // clear this lane's visited bitset (conflict-free: addr%32 == lane)
    #pragma unroll 4
    for (int w = 0; w < VIS_WORDS; ++w) vis[w * 32 + lane] = 0u;

    if (wid < walks) {
        const int b = wid / G;
        const int* __restrict__ nbb = nbrs + (long long)b * N * 3;

        // keys = split(key(42), walks)[wid]
#if JAX_PARTITIONABLE
        U2 k = tf(0u, 42u, 0u, (uint32_t)wid);
#else
        U2 k = tf(0u, 42u, (uint32_t)wid, (uint32_t)(walks + wid));
#endif
        const int f0 = __ldg(centers + wid);
        seq[lane] = f0;
        vis[(f0 >> 5) * 32 + lane] |= 1u << (f0 & 31);

        int i = 1, bs = 1;
        while (i <= L) {
            const int cur = seq[(i - 1) * 32 + lane];
            // issue neighbor loads early; threefry overlaps their latency
            const int n0 = __ldg(nbb + 3 * cur);
            const int n1 = __ldg(nbb + 3 * cur + 1);
            const int n2 = __ldg(nbb + 3 * cur + 2);

            U2 knew, k1; split4_01(k, &knew, &k1);
            U2 ka, kb;   split2(k1, &ka, &kb);
            const uint32_t hi = tf_bits(ka);
            const uint32_t lo = tf_bits(kb);

            const int u0 = ((vis[(n0 >> 5) * 32 + lane] >> (n0 & 31)) & 1u) ? 0 : 1;
            const int u1 = ((vis[(n1 >> 5) * 32 + lane] >> (n1 & 31)) & 1u) ? 0 : 1;
            const int u2 = ((vis[(n2 >> 5) * 32 + lane] >> (n2 & 31)) & 1u) ? 0 : 1;
            const int cnt = u0 + u1 + u2;

            if (cnt > 0) {
                // r = randint(k1, (), 0, cnt) with hi/lo already drawn
                const uint32_t span = (uint32_t)cnt;
                uint32_t m = 65536u % span; m = (m * m) % span;
                const uint32_t r = ((hi % span) * m + (lo % span)) % span;
                const int t = (int)r + 1;
                // first index where cumsum(mask) == r+1
                const int ta = (u0 == t) ? n0 : ((u0 + u1 == t) ? n1 : n2);
                seq[i * 32 + lane] = ta;
                vis[(ta >> 5) * 32 + lane] |= 1u << (ta & 31);
                bs = 1; ++i;
            } else {
                // backtrack path (statistically ~never taken with random graphs,
                // but required for bit-exactness)
                U2 k2, k3; split4_23(k, &k2, &k3);
                int bsc = bs, found = 0, ta = 0;
                U2 kk = k2;
                while (!found && i > bsc) {
                    U2 kkn, kp; split2(kk, &kkn, &kp);
                    const int back = seq[(i - bsc - 1) * 32 + lane];
                    const int b0 = __ldg(nbb + 3 * back);
                    const int b1 = __ldg(nbb + 3 * back + 1);
                    const int b2 = __ldg(nbb + 3 * back + 2);
                    const int m0 = ((vis[(b0 >> 5) * 32 + lane] >> (b0 & 31)) & 1u) ? 0 : 1;
                    const int m1 = ((vis[(b1 >> 5) * 32 + lane] >> (b1 & 31)) & 1u) ? 0 : 1;
                    const int m2 = ((vis[(b2 >> 5) * 32 + lane] >> (b2 & 31)) & 1u) ? 0 : 1;
                    const int bc = m0 + m1 + m2;
                    if (bc > 0) {
                        found = 1;
                        const int t = (int)jrandint(kp, (uint32_t)bc) + 1;
                        ta = (m0 == t) ? b0 : ((m0 + m1 == t) ? b1 : b2);
                    } else {
                        bsc += 2;
                    }
                    kk = kkn;
                }
                if (found) {
                    const int inew = i - bsc;
                    for (int j = inew; j < i; ++j) seq[j * 32 + lane] = ta;
                    vis[(ta >> 5) * 32 + lane] |= 1u << (ta & 31);
                    bs = bsc; i = inew + 1;
                } else {
                    const int ta2 = (int)jrandint(k3, (uint32_t)N);
                    seq[i * 32 + lane] = ta2;
                    vis[(ta2 >> 5) * 32 + lane] |= 1u << (ta2 & 31);
                    bs = 1; ++i;
                }
            }
            k = knew;
        }
    }

    __syncwarp();

    // Fused gather + recenter: out[wg, pos, :] = xyz[b, seq[pos]] - xyz[b, center]
    // Lanes cover positions -> consecutive 12B rows -> coalesced 384B stores.
    const int blk0 = blockIdx.x * 32;
    for (int w = 0; w < 32; ++w) {
        const int wg = blk0 + w;
        if (wg >= walks) break;
        const int bb = wg / G;
        const float* __restrict__ xb = xyz + (long long)bb * N * 3;
        const int c0 = __ldg(centers + wg);
        const float cx = __ldg(xb + 3 * c0);
        const float cy = __ldg(xb + 3 * c0 + 1);
        const float cz = __ldg(xb + 3 * c0 + 2);
        for (int pos = lane; pos <= L; pos += 32) {
            const int node = seq[pos * 32 + w];
            const long long o = ((long long)wg * (L + 1) + pos) * 3;
            out[o]     = __ldg(xb + 3 * node)     - cx;
            out[o + 1] = __ldg(xb + 3 * node + 1) - cy;
            out[o + 2] = __ldg(xb + 3 * node + 2) - cz;
        }
    }
}

extern "C" void kernel_launch(void* const* d_in, const int* in_sizes, int n_in,
                              void* d_out, int out_size) {
    const float* xyz     = (const float*)d_in[0];
    const int*   nbrs    = (const int*)d_in[1];
    const int*   centers = (const int*)d_in[2];
    const int*   pN      = (const int*)d_in[3];   // n_faces (device scalar)

    const int walks = in_sizes[2];                // B*G
    const int L = out_size / (walks * 3) - 1;     // seq_len derived from output shape

    cudaFuncSetAttribute(walk_gather_kernel,
                         cudaFuncAttributeMaxDynamicSharedMemorySize, SMEM_BYTES);

    const int blocks = (walks + 31) / 32;
    walk_gather_kernel<<<blocks, 32, SMEM_BYTES>>>(
        xyz, nbrs, centers, pN, (float*)d_out, in_sizes[0], walks, L);
}

// round 2
// speedup vs baseline: 1.1542x; 1.1542x over previous
#include <cuda_runtime.h>
#include <stdint.h>

// jax_threefry_partitionable=True semantics (verified rel_err==0 in round 1)

#define VIS_WORDS 640              // bitset words: covers n_faces up to 20480
#define SEQ_CAP   64               // L+1
#define MAXW      4096             // B*G for this problem
#define TCAP      64               // precomputed iterations per walk
// smem: vis[640][32] + seq[64][32] + rnd[64][32]
#define SMEM_BYTES ((VIS_WORDS * 32 + SEQ_CAP * 32 + TCAP * 32) * 4)

struct U2 { uint32_t x, y; };

__device__ U2       g_chain[TCAP * MAXW];   // [t][w] key-chain values
__device__ uint32_t g_r23[TCAP * MAXW];     // [t][w] packed r2 | (r3<<8)

// Threefry-2x32, 20 rounds — exact JAX/Random123 schedule.
__device__ __forceinline__ U2 tf(uint32_t k0, uint32_t k1, uint32_t x0, uint32_t x1) {
    uint32_t ks2 = k0 ^ k1 ^ 0x1BD11BDAu;
    x0 += k0; x1 += k1;
#define TF_R(r) { x0 += x1; x1 = __funnelshift_l(x1, x1, (r)); x1 ^= x0; }
    TF_R(13) TF_R(15) TF_R(26) TF_R(6)
    x0 += k1;  x1 += ks2 + 1u;
    TF_R(17) TF_R(29) TF_R(16) TF_R(24)
    x0 += ks2; x1 += k0 + 2u;
    TF_R(13) TF_R(15) TF_R(26) TF_R(6)
    x0 += k0;  x1 += k1 + 3u;
    TF_R(17) TF_R(29) TF_R(16) TF_R(24)
    x0 += k1;  x1 += ks2 + 4u;
    TF_R(13) TF_R(15) TF_R(26) TF_R(6)
    x0 += ks2; x1 += k0 + 5u;
#undef TF_R
    U2 o; o.x = x0; o.y = x1; return o;
}

__device__ __forceinline__ uint32_t tf_bits(U2 k) {          // random_bits(key,32,())
    U2 o = tf(k.x, k.y, 0u, 0u);
    return o.x ^ o.y;
}
__device__ __forceinline__ uint32_t jrandint(U2 k, uint32_t span) { // randint(k,(),0,span)
    U2 ka = tf(k.x, k.y, 0u, 0u);
    U2 kb = tf(k.x, k.y, 0u, 1u);
    uint32_t h = tf_bits(ka), l = tf_bits(kb);
    uint32_t m = 65536u % span; m = (m * m) % span;
    return ((h % span) * m + (l % span)) % span;
}

// ───────────────────────── Kernel A: serial key chains ─────────────────────────
__global__ void __launch_bounds__(32, 1)
chain_kernel(int walks) {
    const int w = blockIdx.x * 32 + threadIdx.x;
    if (w >= walks) return;
    U2 k = tf(0u, 42u, 0u, (uint32_t)w);        // split(key(42), walks)[w]
    #pragma unroll 1
    for (int t = 0; t < TCAP; ++t) {
        g_chain[t * walks + w] = k;
        k = tf(k.x, k.y, 0u, 0u);               // knew = split4[0]
    }
}

// ─────────────────── Kernel B: per-iteration draws, chip-parallel ───────────────
__global__ void __launch_bounds__(256)
rand_kernel(int total) {                        // total = TCAP * walks
    const int idx = blockIdx.x * 256 + threadIdx.x;
    if (idx >= total) return;
    U2 k  = g_chain[idx];
    U2 k1 = tf(k.x, k.y, 0u, 1u);               // split4[1]
    U2 ka = tf(k1.x, k1.y, 0u, 0u);             // split2(k1)
    U2 kb = tf(k1.x, k1.y, 0u, 1u);
    uint32_t h = tf_bits(ka), l = tf_bits(kb);
    // span=2: m = 65536%2 = 0 -> r = l % 2
    uint32_t r2 = l & 1u;
    // span=3: m = (65536%3)^2 % 3 = 1 -> r = (h%3 + l%3) % 3
    uint32_t r3 = ((h % 3u) + (l % 3u)) % 3u;
    g_r23[idx] = r2 | (r3 << 8);
}

// key for body-iteration `it` (0-based); slow-path helper, essentially never >= TCAP
__device__ __noinline__ U2 key_for_iter(int it, int w, int walks) {
    if (it < TCAP) return g_chain[it * walks + w];
    U2 k = g_chain[(TCAP - 1) * walks + w];
    for (int j = TCAP - 1; j < it; ++j) k = tf(k.x, k.y, 0u, 0u);
    return k;
}

// ───────────────────── Kernel C: the walk + fused gather ───────────────────────
__global__ void __launch_bounds__(32, 1)
walk_gather_kernel(const float* __restrict__ xyz,
                   const int*   __restrict__ nbrs,
                   const int*   __restrict__ centers,
                   const int*   __restrict__ pN,
                   float*       __restrict__ out,
                   int xyz_total, int walks, int L)
{
    extern __shared__ uint32_t sm[];
    uint32_t* vis = sm;                                   // [VIS_WORDS][32]
    int*      seq = (int*)(sm + VIS_WORDS * 32);          // [SEQ_CAP][32]
    uint32_t* rnd = sm + VIS_WORDS * 32 + SEQ_CAP * 32;   // [TCAP][32]

    const int lane = threadIdx.x;
    const int wid  = blockIdx.x * 32 + lane;
    const int N    = *pN;
    const int B    = xyz_total / (3 * N);
    const int G    = walks / B;

    // clear bitset (addr%32 == lane: conflict-free)
    #pragma unroll 4
    for (int w = 0; w < VIS_WORDS; ++w) vis[w * 32 + lane] = 0u;

    // stage precomputed draws into shared (coalesced LDGs, off critical path)
    if (wid < walks) {
        #pragma unroll 8
        for (int t = 0; t < TCAP; ++t)
            rnd[t * 32 + lane] = g_r23[t * walks + wid];
    }

    if (wid < walks) {
        const int b = wid / G;
        const int* __restrict__ nbb = nbrs + (long long)b * N * 3;

        const int f0 = __ldg(centers + wid);
        seq[lane] = f0;
        vis[(f0 >> 5) * 32 + lane] |= 1u << (f0 & 31);

        int i = 1, bs = 1, it = 0;
        int cur = f0;
        while (i <= L) {
            const int n0 = __ldg(nbb + 3 * cur);
            const int n1 = __ldg(nbb + 3 * cur + 1);
            const int n2 = __ldg(nbb + 3 * cur + 2);

            const int u0 = ((vis[(n0 >> 5) * 32 + lane] >> (n0 & 31)) & 1u) ? 0 : 1;
            const int u1 = ((vis[(n1 >> 5) * 32 + lane] >> (n1 & 31)) & 1u) ? 0 : 1;
            const int u2 = ((vis[(n2 >> 5) * 32 + lane] >> (n2 & 31)) & 1u) ? 0 : 1;
            const int cnt = u0 + u1 + u2;

            if (cnt > 0 && it < TCAP) {
                // fast path: division-free select using precomputed r2/r3
                const uint32_t rp = rnd[it * 32 + lane];
                const uint32_t r  = (cnt == 3) ? ((rp >> 8) & 3u)
                                  : (cnt == 2) ? (rp & 1u) : 0u;
                const int t = (int)r + 1;
                const int ta = (u0 == t) ? n0 : ((u0 + u1 == t) ? n1 : n2);
                seq[i * 32 + lane] = ta;
                vis[(ta >> 5) * 32 + lane] |= 1u << (ta & 31);
                cur = ta; bs = 1; ++i;
            } else {
                // slow path (backtrack or iteration overflow) — bit-exact, ~never taken
                U2 kc = key_for_iter(it, wid, walks);
                if (cnt > 0) {
                    U2 k1 = tf(kc.x, kc.y, 0u, 1u);
                    const int t = (int)jrandint(k1, (uint32_t)cnt) + 1;
                    const int ta = (u0 == t) ? n0 : ((u0 + u1 == t) ? n1 : n2);
                    seq[i * 32 + lane] = ta;
                    vis[(ta >> 5) * 32 + lane] |= 1u << (ta & 31);
                    cur = ta; bs = 1; ++i;
                } else {
                    U2 k2 = tf(kc.x, kc.y, 0u, 2u);
                    U2 k3 = tf(kc.x, kc.y, 0u, 3u);
                    int bsc = bs, found = 0, ta = 0;
                    U2 kk = k2;
                    while (!found && i > bsc) {
                        U2 kkn = tf(kk.x, kk.y, 0u, 0u);
                        U2 kp  = tf(kk.x, kk.y, 0u, 1u);
                        const int back = seq[(i - bsc - 1) * 32 + lane];
                        const int b0 = __ldg(nbb + 3 * back);
                        const int b1 = __ldg(nbb + 3 * back + 1);
                        const int b2 = __ldg(nbb + 3 * back + 2);
                        const int m0 = ((vis[(b0 >> 5) * 32 + lane] >> (b0 & 31)) & 1u) ? 0 : 1;
                        const int m1 = ((vis[(b1 >> 5) * 32 + lane] >> (b1 & 31)) & 1u) ? 0 : 1;
                        const int m2 = ((vis[(b2 >> 5) * 32 + lane] >> (b2 & 31)) & 1u) ? 0 : 1;
                        const int bc = m0 + m1 + m2;
                        if (bc > 0) {
                            found = 1;
                            const int t = (int)jrandint(kp, (uint32_t)bc) + 1;
                            ta = (m0 == t) ? b0 : ((m0 + m1 == t) ? b1 : b2);
                        } else {
                            bsc += 2;
                        }
                        kk = kkn;
                    }
                    if (found) {
                        const int inew = i - bsc;
                        for (int j = inew; j < i; ++j) seq[j * 32 + lane] = ta;
                        vis[(ta >> 5) * 32 + lane] |= 1u << (ta & 31);
                        cur = ta; bs = bsc; i = inew + 1;
                    } else {
                        const int ta2 = (int)jrandint(k3, (uint32_t)N);
                        seq[i * 32 + lane] = ta2;
                        vis[(ta2 >> 5) * 32 + lane] |= 1u << (ta2 & 31);
                        cur = ta2; bs = 1; ++i;
                    }
                }
            }
            ++it;
        }
    }

    __syncwarp();

    // Fused gather + recenter, coalesced 12B rows across lanes.
    const int blk0 = blockIdx.x * 32;
    for (int w = 0; w < 32; ++w) {
        const int wg = blk0 + w;
        if (wg >= walks) break;
        const int bb = wg / G;
        const float* __restrict__ xb = xyz + (long long)bb * N * 3;
        const int c0 = __ldg(centers + wg);
        const float cx = __ldg(xb + 3 * c0);
        const float cy = __ldg(xb + 3 * c0 + 1);
        const float cz = __ldg(xb + 3 * c0 + 2);
        for (int pos = lane; pos <= L; pos += 32) {
            const int node = seq[pos * 32 + w];
            const long long o = ((long long)wg * (L + 1) + pos) * 3;
            out[o]     = __ldg(xb + 3 * node)     - cx;
            out[o + 1] = __ldg(xb + 3 * node + 1) - cy;
            out[o + 2] = __ldg(xb + 3 * node + 2) - cz;
        }
    }
}

extern "C" void kernel_launch(void* const* d_in, const int* in_sizes, int n_in,
                              void* d_out, int out_size) {
    const float* xyz     = (const float*)d_in[0];
    const int*   nbrs    = (const int*)d_in[1];
    const int*   centers = (const int*)d_in[2];
    const int*   pN      = (const int*)d_in[3];

    const int walks = in_sizes[2];                  // B*G
    const int L = out_size / (walks * 3) - 1;

    cudaFuncSetAttribute(walk_gather_kernel,
                         cudaFuncAttributeMaxDynamicSharedMemorySize, SMEM_BYTES);

    const int wblocks = (walks + 31) / 32;
    chain_kernel<<<wblocks, 32>>>(walks);

    const int total = TCAP * walks;
    rand_kernel<<<(total + 255) / 256, 256>>>(total);

    walk_gather_kernel<<<wblocks, 32, SMEM_BYTES>>>(
        xyz, nbrs, centers, pN, (float*)d_out, in_sizes[0], walks, L);
}

// round 3
// speedup vs baseline: 1.6287x; 1.4112x over previous
#include <cuda_runtime.h>
#include <stdint.h>

// jax_threefry_partitionable=True semantics (verified rel_err==0 in rounds 1-2)

#define VIS_WORDS 640              // bitset words: covers n_faces up to 20480
#define TCAP      64               // L+1 iterations precomputed
#define THREADS   256

// shared-memory word offsets
#define OFF_VIS   0
#define OFF_SEQ   (VIS_WORDS * 32)            // int seq[64][32]
#define OFF_RND   (OFF_SEQ + TCAP * 32)       // u32 rnd[64][32]
#define OFF_CHX   (OFF_RND + TCAP * 32)       // u32 chain.x[64][32]
#define OFF_CHY   (OFF_CHX + TCAP * 32)       // u32 chain.y[64][32]
#define OFF_CXYZ  (OFF_CHY + TCAP * 32)       // float cxyz[32][3]
#define OFF_DUM   (OFF_CXYZ + 96)
#define SMEM_WORDS (OFF_DUM + 4)
#define SMEM_BYTES (SMEM_WORDS * 4)

struct U2 { uint32_t x, y; };

// Threefry-2x32, 20 rounds — exact JAX/Random123 schedule.
__device__ __forceinline__ U2 tf(uint32_t k0, uint32_t k1, uint32_t x0, uint32_t x1) {
    uint32_t ks2 = k0 ^ k1 ^ 0x1BD11BDAu;
    x0 += k0; x1 += k1;
#define TF_R(r) { x0 += x1; x1 = __funnelshift_l(x1, x1, (r)); x1 ^= x0; }
    TF_R(13) TF_R(15) TF_R(26) TF_R(6)
    x0 += k1;  x1 += ks2 + 1u;
    TF_R(17) TF_R(29) TF_R(16) TF_R(24)
    x0 += ks2; x1 += k0 + 2u;
    TF_R(13) TF_R(15) TF_R(26) TF_R(6)
    x0 += k0;  x1 += k1 + 3u;
    TF_R(17) TF_R(29) TF_R(16) TF_R(24)
    x0 += k1;  x1 += ks2 + 4u;
    TF_R(13) TF_R(15) TF_R(26) TF_R(6)
    x0 += ks2; x1 += k0 + 5u;
#undef TF_R
    U2 o; o.x = x0; o.y = x1; return o;
}

__device__ __forceinline__ uint32_t tf_bits(U2 k) {          // random_bits(key,32,())
    U2 o = tf(k.x, k.y, 0u, 0u);
    return o.x ^ o.y;
}
__device__ __forceinline__ uint32_t jrandint(U2 k, uint32_t span) { // randint(k,(),0,span)
    U2 ka = tf(k.x, k.y, 0u, 0u);
    U2 kb = tf(k.x, k.y, 0u, 1u);
    uint32_t h = tf_bits(ka), l = tf_bits(kb);
    uint32_t m = 65536u % span; m = (m * m) % span;
    return ((h % span) * m + (l % span)) % span;
}

__global__ void __launch_bounds__(THREADS, 1)
fused_walk_kernel(const float* __restrict__ xyz,
                  const int*   __restrict__ nbrs,
                  const int*   __restrict__ centers,
                  const int*   __restrict__ pN,
                  float*       __restrict__ out,
                  int xyz_total, int walks, int L)
{
    extern __shared__ uint32_t sm[];
    uint32_t* vis  = sm + OFF_VIS;     // [VIS_WORDS][32] lane-interleaved
    int*      seq  = (int*)(sm + OFF_SEQ);
    uint32_t* rnd  = sm + OFF_RND;
    uint32_t* chx  = sm + OFF_CHX;
    uint32_t* chy  = sm + OFF_CHY;
    float*    cxyz = (float*)(sm + OFF_CXYZ);
    uint32_t* dum  = sm + OFF_DUM;

    const int tid  = threadIdx.x;
    const int lane = tid & 31;
    const int warp = tid >> 5;
    const int blk0 = blockIdx.x * 32;

    const int N = *pN;
    const int B = xyz_total / (3 * N);
    const int G = walks / B;

    // ── Phase 0: clear bitset + issue L1 prefetch of the neighbor table ──
    #pragma unroll 4
    for (int i = tid; i < VIS_WORDS * 32; i += THREADS) vis[i] = 0u;

    uint32_t acc = 0u;
    {
        // prefetch first ~128KB of this block's batch neighbor table into L1
        const int pb = (blk0 < walks) ? (blk0 / G) : 0;
        const int4* __restrict__ tbl = (const int4*)(nbrs + (long long)pb * N * 3);
        const int n4 = (N * 3) >> 2;
        #pragma unroll 1
        for (int k = 0; k < 32; ++k) {
            int idx = tid + k * THREADS;
            if (idx < n4) {
                int4 v = __ldg(tbl + idx);
                acc ^= (uint32_t)v.x ^ (uint32_t)v.y ^ (uint32_t)v.z ^ (uint32_t)v.w;
            }
        }
    }
    __syncthreads();

    // ── Phase 1: pipelined key chains (warp 0) + per-iteration draws (warps 1-7) ──
    U2 kreg;
    if (warp == 0 && blk0 + lane < walks)
        kreg = tf(0u, 42u, 0u, (uint32_t)(blk0 + lane));   // split(key(42), walks)[wid]

    for (int s = 0; s < 9; ++s) {
        if (warp == 0) {
            if (s < 8 && blk0 + lane < walks) {
                #pragma unroll
                for (int j = 0; j < 8; ++j) {
                    const int t = s * 8 + j;
                    chx[t * 32 + lane] = kreg.x;
                    chy[t * 32 + lane] = kreg.y;
                    kreg = tf(kreg.x, kreg.y, 0u, 0u);     // knew = split4[0]
                }
            }
        } else if (s == 0) {
            if (warp == 1 && blk0 + lane < walks) {
                // init: center coords, seq[0], visited bit for f0
                const int wg = blk0 + lane;
                const int bb = wg / G;
                const float* __restrict__ xb = xyz + (long long)bb * N * 3;
                const int f0 = __ldg(centers + wg);
                cxyz[lane * 3]     = __ldg(xb + 3 * f0);
                cxyz[lane * 3 + 1] = __ldg(xb + 3 * f0 + 1);
                cxyz[lane * 3 + 2] = __ldg(xb + 3 * f0 + 2);
                seq[lane] = f0;
                vis[(f0 >> 5) * 32 + lane] |= 1u << (f0 & 31);
            }
        } else {
            // draws for iterations [(s-1)*8, s*8): 256 tasks over 224 workers
            for (int j = tid - 32; j < 256; j += 224) {
                const int t = (s - 1) * 8 + (j >> 5);
                const int w = j & 31;
                if (blk0 + w < walks) {
                    U2 k;  k.x  = chx[t * 32 + w]; k.y = chy[t * 32 + w];
                    U2 k1 = tf(k.x, k.y, 0u, 1u);          // split4[1]
                    U2 ka = tf(k1.x, k1.y, 0u, 0u);        // split2(k1)
                    U2 kb = tf(k1.x, k1.y, 0u, 1u);
                    const uint32_t h = tf_bits(ka), l = tf_bits(kb);
                    const uint32_t r2 = l & 1u;                         // span=2
                    const uint32_t r3 = ((h % 3u) + (l % 3u)) % 3u;     // span=3
                    rnd[t * 32 + w] = r2 | (r3 << 8);
                }
            }
        }
        __syncthreads();
    }

    // ── Phase 2: the walk (warp 0 only; division-free fast path) ──
    if (warp == 0 && blk0 + lane < walks) {
        const int wid = blk0 + lane;
        const int b = wid / G;
        const int* __restrict__ nbb = nbrs + (long long)b * N * 3;

        int i = 1, bs = 1, it = 0;
        int cur = seq[lane];
        while (i <= L) {
            const uint32_t rp = (it < TCAP) ? rnd[it * 32 + lane] : 0u;  // hoisted off critical path
            const int n0 = __ldg(nbb + 3 * cur);
            const int n1 = __ldg(nbb + 3 * cur + 1);
            const int n2 = __ldg(nbb + 3 * cur + 2);

            const int u0 = ((vis[(n0 >> 5) * 32 + lane] >> (n0 & 31)) & 1u) ? 0 : 1;
            const int u1 = ((vis[(n1 >> 5) * 32 + lane] >> (n1 & 31)) & 1u) ? 0 : 1;
            const int u2 = ((vis[(n2 >> 5) * 32 + lane] >> (n2 & 31)) & 1u) ? 0 : 1;
            const int cnt = u0 + u1 + u2;

            if (cnt > 0 && it < TCAP) {
                const uint32_t r = (cnt == 3) ? ((rp >> 8) & 3u)
                                 : (cnt == 2) ? (rp & 1u) : 0u;
                const int t = (int)r + 1;
                const int ta = (u0 == t) ? n0 : ((u0 + u1 == t) ? n1 : n2);
                seq[i * 32 + lane] = ta;
                vis[(ta >> 5) * 32 + lane] |= 1u << (ta & 31);
                cur = ta; bs = 1; ++i;
            } else {
                // slow path (backtrack or it>=TCAP) — bit-exact, statistically ~never
                U2 kc;
                if (it < TCAP) { kc.x = chx[it * 32 + lane]; kc.y = chy[it * 32 + lane]; }
                else {
                    kc.x = chx[(TCAP - 1) * 32 + lane]; kc.y = chy[(TCAP - 1) * 32 + lane];
                    for (int j = TCAP - 1; j < it; ++j) kc = tf(kc.x, kc.y, 0u, 0u);
                }
                if (cnt > 0) {
                    U2 k1 = tf(kc.x, kc.y, 0u, 1u);
                    const int t = (int)jrandint(k1, (uint32_t)cnt) + 1;
                    const int ta = (u0 == t) ? n0 : ((u0 + u1 == t) ? n1 : n2);
                    seq[i * 32 + lane] = ta;
                    vis[(ta >> 5) * 32 + lane] |= 1u << (ta & 31);
                    cur = ta; bs = 1; ++i;
                } else {
                    U2 k2 = tf(kc.x, kc.y, 0u, 2u);
                    U2 k3 = tf(kc.x, kc.y, 0u, 3u);
                    int bsc = bs, found = 0, ta = 0;
                    U2 kk = k2;
                    while (!found && i > bsc) {
                        U2 kkn = tf(kk.x, kk.y, 0u, 0u);
                        U2 kp  = tf(kk.x, kk.y, 0u, 1u);
                        const int back = seq[(i - bsc - 1) * 32 + lane];
                        const int b0 = __ldg(nbb + 3 * back);
                        const int b1 = __ldg(nbb + 3 * back + 1);
                        const int b2 = __ldg(nbb + 3 * back + 2);
                        const int m0 = ((vis[(b0 >> 5) * 32 + lane] >> (b0 & 31)) & 1u) ? 0 : 1;
                        const int m1 = ((vis[(b1 >> 5) * 32 + lane] >> (b1 & 31)) & 1u) ? 0 : 1;
                        const int m2 = ((vis[(b2 >> 5) * 32 + lane] >> (b2 & 31)) & 1u) ? 0 : 1;
                        const int bc = m0 + m1 + m2;
                        if (bc > 0) {
                            found = 1;
                            const int t = (int)jrandint(kp, (uint32_t)bc) + 1;
                            ta = (m0 == t) ? b0 : ((m0 + m1 == t) ? b1 : b2);
                        } else {
                            bsc += 2;
                        }
                        kk = kkn;
                    }
                    if (found) {
                        const int inew = i - bsc;
                        for (int j = inew; j < i; ++j) seq[j * 32 + lane] = ta;
                        vis[(ta >> 5) * 32 + lane] |= 1u << (ta & 31);
                        cur = ta; bs = bsc; i = inew + 1;
                    } else {
                        const int ta2 = (int)jrandint(k3, (uint32_t)N);
                        seq[i * 32 + lane] = ta2;
                        vis[(ta2 >> 5) * 32 + lane] |= 1u << (ta2 & 31);
                        cur = ta2; bs = 1; ++i;
                    }
                }
            }
            ++it;
        }
    }
    __syncthreads();

    // keep prefetch loads alive (never-true deterministic guard; dum never read)
    if (acc == 0x9E3779B9u) dum[0] = acc;

    // ── Phase 3: gather + recenter with all 8 warps (coalesced, latency-hidden) ──
    const int rows = 32 * (L + 1);
    for (int r = tid; r < rows; r += THREADS) {
        const int w   = r / (L + 1);
        const int pos = r - w * (L + 1);
        const int wg  = blk0 + w;
        if (wg < walks) {
            const int bb = wg / G;
            const float* __restrict__ xb = xyz + (long long)bb * N * 3;
            const int node = seq[pos * 32 + w];
            const long long o = ((long long)wg * (L + 1) + pos) * 3;
            out[o]     = __ldg(xb + 3 * node)     - cxyz[w * 3];
            out[o + 1] = __ldg(xb + 3 * node + 1) - cxyz[w * 3 + 1];
            out[o + 2] = __ldg(xb + 3 * node + 2) - cxyz[w * 3 + 2];
        }
    }
}

extern "C" void kernel_launch(void* const* d_in, const int* in_sizes, int n_in,
                              void* d_out, int out_size) {
    const float* xyz     = (const float*)d_in[0];
    const int*   nbrs    = (const int*)d_in[1];
    const int*   centers = (const int*)d_in[2];
    const int*   pN      = (const int*)d_in[3];

    const int walks = in_sizes[2];                  // B*G
    const int L = out_size / (walks * 3) - 1;       // seq_len

    cudaFuncSetAttribute(fused_walk_kernel,
                         cudaFuncAttributeMaxDynamicSharedMemorySize, SMEM_BYTES);

    const int blocks = (walks + 31) / 32;
    fused_walk_kernel<<<blocks, THREADS, SMEM_BYTES>>>(
        xyz, nbrs, centers, pN, (float*)d_out, in_sizes[0], walks, L);
}

// round 6
// speedup vs baseline: 2.2174x; 1.3614x over previous
#include <cuda_runtime.h>
#include <stdint.h>

// jax_threefry_partitionable=True semantics (verified rel_err==0 in rounds 1-3)

#define NCAP      20480            // max faces supported by smem table / bitset
#define VIS_WORDS 640              // NCAP/32 bitset words per walk
#define TCAP      64               // L+1 iterations precomputed
#define THREADS   256

// shared-memory layout (u32 word offsets)
#define OFF_VIS   0                         // u32 vis[640][32]
#define OFF_SEQ   (OFF_VIS + VIS_WORDS*32)  // int seq[64][32]
#define OFF_RND   (OFF_SEQ + TCAP*32)       // u32 rnd[64][32]
#define OFF_RINGX (OFF_RND + TCAP*32)       // u32 ringx[2][8][32]
#define OFF_RINGY (OFF_RINGX + 512)         // u32 ringy[2][8][32]
#define OFF_P01   (OFF_RINGY + 512)         // u32 p01[NCAP]   (n0 | n1<<16)
#define OFF_N2    (OFF_P01 + NCAP)          // u16 n2[NCAP] -> NCAP/2 words
#define OFF_CXYZ  (OFF_N2 + NCAP/2)         // float cxyz[32][3]
#define SMEM_WORDS (OFF_CXYZ + 96 + 4)
#define SMEM_BYTES (SMEM_WORDS * 4)         // 225,680 B < 232,448 B sm_103a limit

struct U2 { uint32_t x, y; };

// Threefry-2x32, 20 rounds — exact JAX/Random123 schedule.
__device__ __forceinline__ U2 tf(uint32_t k0, uint32_t k1, uint32_t x0, uint32_t x1) {
    uint32_t ks2 = k0 ^ k1 ^ 0x1BD11BDAu;
    x0 += k0; x1 += k1;
#define TF_R(r) { x0 += x1; x1 = __funnelshift_l(x1, x1, (r)); x1 ^= x0; }
    TF_R(13) TF_R(15) TF_R(26) TF_R(6)
    x0 += k1;  x1 += ks2 + 1u;
    TF_R(17) TF_R(29) TF_R(16) TF_R(24)
    x0 += ks2; x1 += k0 + 2u;
    TF_R(13) TF_R(15) TF_R(26) TF_R(6)
    x0 += k0;  x1 += k1 + 3u;
    TF_R(17) TF_R(29) TF_R(16) TF_R(24)
    x0 += k1;  x1 += ks2 + 4u;
    TF_R(13) TF_R(15) TF_R(26) TF_R(6)
    x0 += ks2; x1 += k0 + 5u;
#undef TF_R
    U2 o; o.x = x0; o.y = x1; return o;
}

__device__ __forceinline__ uint32_t tf_bits(U2 k) {          // random_bits(key,32,())
    U2 o = tf(k.x, k.y, 0u, 0u);
    return o.x ^ o.y;
}
__device__ __forceinline__ uint32_t jrandint(U2 k, uint32_t span) { // randint(k,(),0,span)
    U2 ka = tf(k.x, k.y, 0u, 0u);
    U2 kb = tf(k.x, k.y, 0u, 1u);
    uint32_t h = tf_bits(ka), l = tf_bits(kb);
    uint32_t m = 65536u % span; m = (m * m) % span;
    return ((h % span) * m + (l % span)) % span;
}

__global__ void __launch_bounds__(THREADS, 1)
fused_walk_kernel(const float* __restrict__ xyz,
                  const int*   __restrict__ nbrs,
                  const int*   __restrict__ centers,
                  const int*   __restrict__ pN,
                  float*       __restrict__ out,
                  int xyz_total, int walks, int L)
{
    extern __shared__ uint32_t sm[];
    uint32_t* vis   = sm + OFF_VIS;
    int*      seq   = (int*)(sm + OFF_SEQ);
    uint32_t* rnd   = sm + OFF_RND;
    uint32_t* ringx = sm + OFF_RINGX;
    uint32_t* ringy = sm + OFF_RINGY;
    uint32_t* p01s  = sm + OFF_P01;
    uint16_t* n2s   = (uint16_t*)(sm + OFF_N2);
    float*    cxyz  = (float*)(sm + OFF_CXYZ);

    const int tid  = threadIdx.x;
    const int lane = tid & 31;
    const int warp = tid >> 5;
    const int blk0 = blockIdx.x * 32;

    const int N = *pN;
    const int B = xyz_total / (3 * N);
    const int G = walks / B;
    // smem fast path valid when table fits and the whole block is one batch
    const bool use_smem = (N <= NCAP) && (G % 32 == 0);
    const int  pb  = (blk0 < walks) ? (blk0 / G) : 0;
    const int* __restrict__ btab = nbrs + (long long)pb * N * 3;

    // ── Phase 0: clear visited bitset ──
    #pragma unroll 8
    for (int i = tid; i < VIS_WORDS * 32; i += THREADS) vis[i] = 0u;
    __syncthreads();

    // ── Phase 1: serial key chain (warp 0) || rand draws + table pack (warps 1-7) ──
    U2 kreg;
    if (warp == 0 && blk0 + lane < walks)
        kreg = tf(0u, 42u, 0u, (uint32_t)(blk0 + lane));   // split(key(42), walks)[wid]

    const int ngroups = use_smem ? ((N + 3) >> 2) : 0;      // 4 faces per group

    for (int s = 0; s < 9; ++s) {
        if (warp == 0) {
            // produce chain keys for epoch s into ring slot s&1
            if (s < 8 && blk0 + lane < walks) {
                const int slot = (s & 1) * 256;
                #pragma unroll
                for (int j = 0; j < 8; ++j) {
                    ringx[slot + j * 32 + lane] = kreg.x;
                    ringy[slot + j * 32 + lane] = kreg.y;
                    kreg = tf(kreg.x, kreg.y, 0u, 0u);     // knew = split4[0]
                }
            }
        } else {
            if (s == 0 && warp == 1 && blk0 + lane < walks) {
                // init: center coords, seq[0], visited bit for f0
                const int wg = blk0 + lane;
                const int bb = wg / G;
                const float* __restrict__ xb = xyz + (long long)bb * N * 3;
                const int f0 = __ldg(centers + wg);
                cxyz[lane * 3]     = __ldg(xb + 3 * f0);
                cxyz[lane * 3 + 1] = __ldg(xb + 3 * f0 + 1);
                cxyz[lane * 3 + 2] = __ldg(xb + 3 * f0 + 2);
                seq[lane] = f0;
                vis[(f0 >> 5) * 32 + lane] |= 1u << (f0 & 31);
            }
            if (s >= 1) {
                // rand draws for iterations [(s-1)*8, s*8) from ring slot (s-1)&1
                const int slot = ((s - 1) & 1) * 256;
                for (int j = tid - 32; j < 256; j += 224) {
                    const int t = (s - 1) * 8 + (j >> 5);
                    const int w = j & 31;
                    if (blk0 + w < walks) {
                        U2 k;  k.x = ringx[slot + (t & 7) * 32 + w];
                               k.y = ringy[slot + (t & 7) * 32 + w];
                        U2 k1 = tf(k.x, k.y, 0u, 1u);          // split4[1]
                        U2 ka = tf(k1.x, k1.y, 0u, 0u);        // split2(k1)
                        U2 kb = tf(k1.x, k1.y, 0u, 1u);
                        const uint32_t h = tf_bits(ka), l = tf_bits(kb);
                        const uint32_t r2 = l & 1u;                      // span=2
                        const uint32_t r3 = ((h % 3u) + (l % 3u)) % 3u;  // span=3
                        rnd[t * 32 + w] = r2 | (r3 << 8);
                    }
                }
            }
            // pack quota for this epoch: 3 strided group-slices per thread
            if (use_smem) {
                const int4* __restrict__ tbl4 = (const int4*)btab;
                #pragma unroll
                for (int m = 0; m < 3; ++m) {
                    const int g = (tid - 32) + 224 * (s * 3 + m);
                    if (g < ngroups) {
                        const int f = g * 4;
                        if (f + 3 < N) {
                            const int4 a = __ldg(tbl4 + 3 * g);
                            const int4 b = __ldg(tbl4 + 3 * g + 1);
                            const int4 c = __ldg(tbl4 + 3 * g + 2);
                            p01s[f]     = (uint32_t)a.x | ((uint32_t)a.y << 16);
                            n2s [f]     = (uint16_t)a.z;
                            p01s[f + 1] = (uint32_t)a.w | ((uint32_t)b.x << 16);
                            n2s [f + 1] = (uint16_t)b.y;
                            p01s[f + 2] = (uint32_t)b.z | ((uint32_t)b.w << 16);
                            n2s [f + 2] = (uint16_t)c.x;
                            p01s[f + 3] = (uint32_t)c.y | ((uint32_t)c.z << 16);
                            n2s [f + 3] = (uint16_t)c.w;
                        } else {
                            #pragma unroll 1
                            for (int ff = f; ff < N; ++ff) {
                                const int x0 = __ldg(btab + 3 * ff);
                                const int x1 = __ldg(btab + 3 * ff + 1);
                                const int x2 = __ldg(btab + 3 * ff + 2);
                                p01s[ff] = (uint32_t)x0 | ((uint32_t)x1 << 16);
                                n2s [ff] = (uint16_t)x2;
                            }
                        }
                    }
                }
            }
        }
        __syncthreads();
    }

    // ── Phase 2: the walk (warp 0; all-smem fast path) ──
    if (warp == 0 && blk0 + lane < walks) {
        const int wid = blk0 + lane;
        const int b = wid / G;
        const int* __restrict__ nbb = nbrs + (long long)b * N * 3;

        int i = 1, bs = 1, it = 0;
        int cur = seq[lane];
        while (i <= L) {
            const uint32_t rp = (it < TCAP) ? rnd[it * 32 + lane] : 0u;
            int n0, n1, n2;
            if (use_smem) {
                const uint32_t p = p01s[cur];
                n0 = (int)(p & 0xFFFFu);
                n1 = (int)(p >> 16);
                n2 = (int)n2s[cur];
            } else {
                n0 = __ldg(nbb + 3 * cur);
                n1 = __ldg(nbb + 3 * cur + 1);
                n2 = __ldg(nbb + 3 * cur + 2);
            }

            const int u0 = ((vis[(n0 >> 5) * 32 + lane] >> (n0 & 31)) & 1u) ? 0 : 1;
            const int u1 = ((vis[(n1 >> 5) * 32 + lane] >> (n1 & 31)) & 1u) ? 0 : 1;
            const int u2 = ((vis[(n2 >> 5) * 32 + lane] >> (n2 & 31)) & 1u) ? 0 : 1;
            const int cnt = u0 + u1 + u2;

            if (cnt > 0 && it < TCAP) {
                const uint32_t r = (cnt == 3) ? ((rp >> 8) & 3u)
                                 : (cnt == 2) ? (rp & 1u) : 0u;
                const int t = (int)r + 1;
                const int ta = (u0 == t) ? n0 : ((u0 + u1 == t) ? n1 : n2);
                seq[i * 32 + lane] = ta;
                vis[(ta >> 5) * 32 + lane] |= 1u << (ta & 31);
                cur = ta; bs = 1; ++i;
            } else {
                // slow path (backtrack or it>=TCAP) — bit-exact, statistically ~never.
                // Recompute the chain key for this iteration from the base key.
                U2 kc = tf(0u, 42u, 0u, (uint32_t)wid);
                #pragma unroll 1
                for (int j = 0; j < it; ++j) kc = tf(kc.x, kc.y, 0u, 0u);
                if (cnt > 0) {
                    U2 k1 = tf(kc.x, kc.y, 0u, 1u);
                    const int t = (int)jrandint(k1, (uint32_t)cnt) + 1;
                    const int ta = (u0 == t) ? n0 : ((u0 + u1 == t) ? n1 : n2);
                    seq[i * 32 + lane] = ta;
                    vis[(ta >> 5) * 32 + lane] |= 1u << (ta & 31);
                    cur = ta; bs = 1; ++i;
                } else {
                    U2 k2 = tf(kc.x, kc.y, 0u, 2u);
                    U2 k3 = tf(kc.x, kc.y, 0u, 3u);
                    int bsc = bs, found = 0, ta = 0;
                    U2 kk = k2;
                    #pragma unroll 1
                    while (!found && i > bsc) {
                        U2 kkn = tf(kk.x, kk.y, 0u, 0u);
                        U2 kp  = tf(kk.x, kk.y, 0u, 1u);
                        const int back = seq[(i - bsc - 1) * 32 + lane];
                        const int b0 = __ldg(nbb + 3 * back);
                        const int b1 = __ldg(nbb + 3 * back + 1);
                        const int b2 = __ldg(nbb + 3 * back + 2);
                        const int m0 = ((vis[(b0 >> 5) * 32 + lane] >> (b0 & 31)) & 1u) ? 0 : 1;
                        const int m1 = ((vis[(b1 >> 5) * 32 + lane] >> (b1 & 31)) & 1u) ? 0 : 1;
                        const int m2 = ((vis[(b2 >> 5) * 32 + lane] >> (b2 & 31)) & 1u) ? 0 : 1;
                        const int bc = m0 + m1 + m2;
                        if (bc > 0) {
                            found = 1;
                            const int t = (int)jrandint(kp, (uint32_t)bc) + 1;
                            ta = (m0 == t) ? b0 : ((m0 + m1 == t) ? b1 : b2);
                        } else {
                            bsc += 2;
                        }
                        kk = kkn;
                    }
                    if (found) {
                        const int inew = i - bsc;
                        for (int j = inew; j < i; ++j) seq[j * 32 + lane] = ta;
                        vis[(ta >> 5) * 32 + lane] |= 1u << (ta & 31);
                        cur = ta; bs = bsc; i = inew + 1;
                    } else {
                        const int ta2 = (int)jrandint(k3, (uint32_t)N);
                        seq[i * 32 + lane] = ta2;
                        vis[(ta2 >> 5) * 32 + lane] |= 1u << (ta2 & 31);
                        cur = ta2; bs = 1; ++i;
                    }
                }
            }
            ++it;
        }
    }
    __syncthreads();

    // ── Phase 3: gather + recenter with all 8 warps (coalesced, latency-hidden) ──
    const int rows = 32 * (L + 1);
    for (int r = tid; r < rows; r += THREADS) {
        const int w   = r / (L + 1);
        const int pos = r - w * (L + 1);
        const int wg  = blk0 + w;
        if (wg < walks) {
            const int bb = wg / G;
            const float* __restrict__ xb = xyz + (long long)bb * N * 3;
            const int node = seq[pos * 32 + w];
            const long long o = ((long long)wg * (L + 1) + pos) * 3;
            out[o]     = __ldg(xb + 3 * node)     - cxyz[w * 3];
            out[o + 1] = __ldg(xb + 3 * node + 1) - cxyz[w * 3 + 1];
            out[o + 2] = __ldg(xb + 3 * node + 2) - cxyz[w * 3 + 2];
        }
    }
}

extern "C" void kernel_launch(void* const* d_in, const int* in_sizes, int n_in,
                              void* d_out, int out_size) {
    const float* xyz     = (const float*)d_in[0];
    const int*   nbrs    = (const int*)d_in[1];
    const int*   centers = (const int*)d_in[2];
    const int*   pN      = (const int*)d_in[3];

    const int walks = in_sizes[2];                  // B*G
    const int L = out_size / (walks * 3) - 1;       // seq_len

    cudaFuncSetAttribute(fused_walk_kernel,
                         cudaFuncAttributeMaxDynamicSharedMemorySize, SMEM_BYTES);

    const int blocks = (walks + 31) / 32;
    fused_walk_kernel<<<blocks, THREADS, SMEM_BYTES>>>(
        xyz, nbrs, centers, pN, (float*)d_out, in_sizes[0], walks, L);
}

// round 8
// speedup vs baseline: 2.4929x; 1.1242x over previous
#include <cuda_runtime.h>
#include <stdint.h>

// jax_threefry_partitionable=True semantics (verified rel_err==0 in rounds 1-6)

#define NCAP      20480            // max faces supported by smem table / bitset
#define VIS_WORDS 640              // NCAP/32 bitset words per walk
#define TCAP      64               // L+1 iterations precomputed
#define THREADS   256

// shared-memory layout (u32 word offsets)
#define OFF_VIS   0                         // u32 vis[640][32]
#define OFF_SEQ   (OFF_VIS + VIS_WORDS*32)  // int seq[64][32]
#define OFF_RND   (OFF_SEQ + TCAP*32)       // u32 rnd[64][32]
#define OFF_RINGX (OFF_RND + TCAP*32)       // u32 ringx[2][8][32]
#define OFF_RINGY (OFF_RINGX + 512)         // u32 ringy[2][8][32]
#define OFF_P01   (OFF_RINGY + 512)         // u32 p01[NCAP]   (n0 | n1<<16)
#define OFF_N2    (OFF_P01 + NCAP)          // u16 n2[NCAP] -> NCAP/2 words
#define OFF_CXYZ  (OFF_N2 + NCAP/2)         // float cxyz[32][3]
#define SMEM_WORDS (OFF_CXYZ + 96 + 4)
#define SMEM_BYTES (SMEM_WORDS * 4)         // 225,680 B < 232,448 B sm_103a limit

struct U2 { uint32_t x, y; };

// Threefry-2x32, 20 rounds — exact JAX/Random123 schedule.
__device__ __forceinline__ U2 tf(uint32_t k0, uint32_t k1, uint32_t x0, uint32_t x1) {
    uint32_t ks2 = k0 ^ k1 ^ 0x1BD11BDAu;
    x0 += k0; x1 += k1;
#define TF_R(r) { x0 += x1; x1 = __funnelshift_l(x1, x1, (r)); x1 ^= x0; }
    TF_R(13) TF_R(15) TF_R(26) TF_R(6)
    x0 += k1;  x1 += ks2 + 1u;
    TF_R(17) TF_R(29) TF_R(16) TF_R(24)
    x0 += ks2; x1 += k0 + 2u;
    TF_R(13) TF_R(15) TF_R(26) TF_R(6)
    x0 += k0;  x1 += k1 + 3u;
    TF_R(17) TF_R(29) TF_R(16) TF_R(24)
    x0 += k1;  x1 += ks2 + 4u;
    TF_R(13) TF_R(15) TF_R(26) TF_R(6)
    x0 += ks2; x1 += k0 + 5u;
#undef TF_R
    U2 o; o.x = x0; o.y = x1; return o;
}

__device__ __forceinline__ uint32_t tf_bits(U2 k) {          // random_bits(key,32,())
    U2 o = tf(k.x, k.y, 0u, 0u);
    return o.x ^ o.y;
}
__device__ __forceinline__ uint32_t jrandint(U2 k, uint32_t span) { // randint(k,(),0,span)
    U2 ka = tf(k.x, k.y, 0u, 0u);
    U2 kb = tf(k.x, k.y, 0u, 1u);
    uint32_t h = tf_bits(ka), l = tf_bits(kb);
    uint32_t m = 65536u % span; m = (m * m) % span;
    return ((h % span) * m + (l % span)) % span;
}

// Walk state (warp 1, one walk per lane)
struct WalkState { int i, bs, it, cur; };

// Advance the walk while i<=L and it<itlim. Fast path uses smem table + rnd;
// slow path (backtrack / it>=TCAP) recomputes keys from the base key (bit-exact).
__device__ __forceinline__ void walk_advance(
    WalkState& st, int itlim, int L, int lane, int wid, int N,
    bool use_smem, const int* __restrict__ nbb,
    uint32_t* __restrict__ vis, int* __restrict__ seq,
    const uint32_t* __restrict__ rnd,
    const uint32_t* __restrict__ p01s, const uint16_t* __restrict__ n2s)
{
    int i = st.i, bs = st.bs, it = st.it, cur = st.cur;
    while (i <= L && it < itlim) {
        const uint32_t rp = (it < TCAP) ? rnd[it * 32 + lane] : 0u;
        int n0, n1, n2;
        if (use_smem) {
            const uint32_t p = p01s[cur];
            n0 = (int)(p & 0xFFFFu);
            n1 = (int)(p >> 16);
            n2 = (int)n2s[cur];
        } else {
            n0 = __ldg(nbb + 3 * cur);
            n1 = __ldg(nbb + 3 * cur + 1);
            n2 = __ldg(nbb + 3 * cur + 2);
        }

        const int u0 = ((vis[(n0 >> 5) * 32 + lane] >> (n0 & 31)) & 1u) ? 0 : 1;
        const int u1 = ((vis[(n1 >> 5) * 32 + lane] >> (n1 & 31)) & 1u) ? 0 : 1;
        const int u2 = ((vis[(n2 >> 5) * 32 + lane] >> (n2 & 31)) & 1u) ? 0 : 1;
        const int cnt = u0 + u1 + u2;

        if (cnt > 0 && it < TCAP) {
            const uint32_t r = (cnt == 3) ? ((rp >> 8) & 3u)
                             : (cnt == 2) ? (rp & 1u) : 0u;
            const int t = (int)r + 1;
            const int ta = (u0 == t) ? n0 : ((u0 + u1 == t) ? n1 : n2);
            seq[i * 32 + lane] = ta;
            vis[(ta >> 5) * 32 + lane] |= 1u << (ta & 31);
            cur = ta; bs = 1; ++i;
        } else {
            // slow path — recompute chain key for iteration `it` from base key
            U2 kc = tf(0u, 42u, 0u, (uint32_t)wid);
            #pragma unroll 1
            for (int j = 0; j < it; ++j) kc = tf(kc.x, kc.y, 0u, 0u);
            if (cnt > 0) {
                U2 k1 = tf(kc.x, kc.y, 0u, 1u);
                const int t = (int)jrandint(k1, (uint32_t)cnt) + 1;
                const int ta = (u0 == t) ? n0 : ((u0 + u1 == t) ? n1 : n2);
                seq[i * 32 + lane] = ta;
                vis[(ta >> 5) * 32 + lane] |= 1u << (ta & 31);
                cur = ta; bs = 1; ++i;
            } else {
                U2 k2 = tf(kc.x, kc.y, 0u, 2u);
                U2 k3 = tf(kc.x, kc.y, 0u, 3u);
                int bsc = bs, found = 0, ta = 0;
                U2 kk = k2;
                #pragma unroll 1
                while (!found && i > bsc) {
                    U2 kkn = tf(kk.x, kk.y, 0u, 0u);
                    U2 kp  = tf(kk.x, kk.y, 0u, 1u);
                    const int back = seq[(i - bsc - 1) * 32 + lane];
                    const int b0 = __ldg(nbb + 3 * back);
                    const int b1 = __ldg(nbb + 3 * back + 1);
                    const int b2 = __ldg(nbb + 3 * back + 2);
                    const int m0 = ((vis[(b0 >> 5) * 32 + lane] >> (b0 & 31)) & 1u) ? 0 : 1;
                    const int m1 = ((vis[(b1 >> 5) * 32 + lane] >> (b1 & 31)) & 1u) ? 0 : 1;
                    const int m2 = ((vis[(b2 >> 5) * 32 + lane] >> (b2 & 31)) & 1u) ? 0 : 1;
                    const int bc = m0 + m1 + m2;
                    if (bc > 0) {
                        found = 1;
                        const int t = (int)jrandint(kp, (uint32_t)bc) + 1;
                        ta = (m0 == t) ? b0 : ((m0 + m1 == t) ? b1 : b2);
                    } else {
                        bsc += 2;
                    }
                    kk = kkn;
                }
                if (found) {
                    const int inew = i - bsc;
                    for (int j = inew; j < i; ++j) seq[j * 32 + lane] = ta;
                    vis[(ta >> 5) * 32 + lane] |= 1u << (ta & 31);
                    cur = ta; bs = bsc; i = inew + 1;
                } else {
                    const int ta2 = (int)jrandint(k3, (uint32_t)N);
                    seq[i * 32 + lane] = ta2;
                    vis[(ta2 >> 5) * 32 + lane] |= 1u << (ta2 & 31);
                    cur = ta2; bs = 1; ++i;
                }
            }
        }
        ++it;
    }
    st.i = i; st.bs = bs; st.it = it; st.cur = cur;
}

__global__ void __launch_bounds__(THREADS, 1)
fused_walk_kernel(const float* __restrict__ xyz,
                  const int*   __restrict__ nbrs,
                  const int*   __restrict__ centers,
                  const int*   __restrict__ pN,
                  float*       __restrict__ out,
                  int xyz_total, int walks, int L)
{
    extern __shared__ uint32_t sm[];
    uint32_t* vis   = sm + OFF_VIS;
    int*      seq   = (int*)(sm + OFF_SEQ);
    uint32_t* rnd   = sm + OFF_RND;
    uint32_t* ringx = sm + OFF_RINGX;
    uint32_t* ringy = sm + OFF_RINGY;
    uint32_t* p01s  = sm + OFF_P01;
    uint16_t* n2s   = (uint16_t*)(sm + OFF_N2);
    float*    cxyz  = (float*)(sm + OFF_CXYZ);

    const int tid  = threadIdx.x;
    const int lane = tid & 31;
    const int warp = tid >> 5;
    const int blk0 = blockIdx.x * 32;

    const int N = *pN;
    const int B = xyz_total / (3 * N);
    const int G = walks / B;
    const bool use_smem = (N <= NCAP) && (G % 32 == 0);
    const int  pb  = (blk0 < walks) ? (blk0 / G) : 0;
    const int* __restrict__ btab = nbrs + (long long)pb * N * 3;
    const bool valid = (blk0 + lane < walks);

    // ── Phase 0: clear bitset; warp 7 does per-walk init ──
    #pragma unroll 8
    for (int i = tid; i < VIS_WORDS * 32; i += THREADS) vis[i] = 0u;
    if (warp == 7 && valid) {
        const int wg = blk0 + lane;
        const int bb = wg / G;
        const float* __restrict__ xb = xyz + (long long)bb * N * 3;
        const int f0 = __ldg(centers + wg);
        cxyz[lane * 3]     = __ldg(xb + 3 * f0);
        cxyz[lane * 3 + 1] = __ldg(xb + 3 * f0 + 1);
        cxyz[lane * 3 + 2] = __ldg(xb + 3 * f0 + 2);
        seq[lane] = f0;
        vis[(f0 >> 5) * 32 + lane] |= 1u << (f0 & 31);
    }
    __syncthreads();

    // ── Pipelined epochs: chain (w0) | pack s<=3 (w1-7) | rand s>=1 (w2-7) | walk s>=4 (w1) ──
    U2 kreg;
    if (warp == 0 && valid)
        kreg = tf(0u, 42u, 0u, (uint32_t)(blk0 + lane));   // split(key(42), walks)[wid]

    const int wid1 = blk0 + lane;
    const int* __restrict__ nbb1 = nbrs + (long long)((blk0 + lane < walks) ? wid1 / G : 0) * N * 3;
    WalkState st; st.i = 1; st.bs = 1; st.it = 0; st.cur = (warp == 1 && valid) ? seq[lane] : 0;

    const int ngroups = use_smem ? ((N + 3) >> 2) : 0;
    const int chunk   = (ngroups + 3) >> 2;                 // pack quarter per epoch

    for (int s = 0; s <= 8; ++s) {
        if (warp == 0) {
            if (s < 8 && valid) {
                const int slot = (s & 1) * 256;
                #pragma unroll
                for (int j = 0; j < 8; ++j) {
                    ringx[slot + j * 32 + lane] = kreg.x;
                    ringy[slot + j * 32 + lane] = kreg.y;
                    kreg = tf(kreg.x, kreg.y, 0u, 0u);     // knew = split4[0]
                }
            }
        } else {
            // pack quarter s (epochs 0..3, warps 1-7)
            if (use_smem && s <= 3) {
                const int4* __restrict__ tbl4 = (const int4*)btab;
                const int gend = min(chunk * (s + 1), ngroups);
                #pragma unroll 1
                for (int g = chunk * s + (tid - 32); g < gend; g += 224) {
                    const int f = g * 4;
                    if (f + 3 < N) {
                        const int4 a = __ldg(tbl4 + 3 * g);
                        const int4 b = __ldg(tbl4 + 3 * g + 1);
                        const int4 c = __ldg(tbl4 + 3 * g + 2);
                        p01s[f]     = (uint32_t)a.x | ((uint32_t)a.y << 16);
                        n2s [f]     = (uint16_t)a.z;
                        p01s[f + 1] = (uint32_t)a.w | ((uint32_t)b.x << 16);
                        n2s [f + 1] = (uint16_t)b.y;
                        p01s[f + 2] = (uint32_t)b.z | ((uint32_t)b.w << 16);
                        n2s [f + 2] = (uint16_t)c.x;
                        p01s[f + 3] = (uint32_t)c.y | ((uint32_t)c.z << 16);
                        n2s [f + 3] = (uint16_t)c.w;
                    } else {
                        #pragma unroll 1
                        for (int ff = f; ff < N; ++ff) {
                            const int x0 = __ldg(btab + 3 * ff);
                            const int x1 = __ldg(btab + 3 * ff + 1);
                            const int x2 = __ldg(btab + 3 * ff + 2);
                            p01s[ff] = (uint32_t)x0 | ((uint32_t)x1 << 16);
                            n2s [ff] = (uint16_t)x2;
                        }
                    }
                }
            }
            // rand draws for epoch s-1 (warps 2-7, 192 workers, 256 tasks)
            if (s >= 1 && warp >= 2) {
                const int slot = ((s - 1) & 1) * 256;
                #pragma unroll 1
                for (int j = tid - 64; j < 256; j += 192) {
                    const int t = (s - 1) * 8 + (j >> 5);
                    const int w = j & 31;
                    if (blk0 + w < walks) {
                        U2 k;  k.x = ringx[slot + (t & 7) * 32 + w];
                               k.y = ringy[slot + (t & 7) * 32 + w];
                        U2 k1 = tf(k.x, k.y, 0u, 1u);          // split4[1]
                        U2 ka = tf(k1.x, k1.y, 0u, 0u);        // split2(k1)
                        U2 kb = tf(k1.x, k1.y, 0u, 1u);
                        const uint32_t h = tf_bits(ka), l = tf_bits(kb);
                        const uint32_t r2 = l & 1u;                      // span=2
                        const uint32_t r3 = ((h % 3u) + (l % 3u)) % 3u;  // span=3
                        rnd[t * 32 + w] = r2 | (r3 << 8);
                    }
                }
            }
            // pipelined walk (warp 1, epochs 4..8): it < 8s-16 <= published 8(s-1)
            if (warp == 1 && s >= 4 && valid) {
                int lim = 8 * s - 16; if (lim > TCAP) lim = TCAP;
                walk_advance(st, lim, L, lane, wid1, N, use_smem, nbb1,
                             vis, seq, rnd, p01s, n2s);
            }
        }
        __syncthreads();
    }

    // ── Walk tail (all rnd published) ──
    if (warp == 1 && valid)
        walk_advance(st, 0x40000000, L, lane, wid1, N, use_smem, nbb1,
                     vis, seq, rnd, p01s, n2s);
    __syncthreads();

    // ── Gather + recenter with all 8 warps (coalesced, latency-hidden) ──
    const int rows = 32 * (L + 1);
    for (int r = tid; r < rows; r += THREADS) {
        const int w   = r / (L + 1);
        const int pos = r - w * (L + 1);
        const int wg  = blk0 + w;
        if (wg < walks) {
            const int bb = wg / G;
            const float* __restrict__ xb = xyz + (long long)bb * N * 3;
            const int node = seq[pos * 32 + w];
            const long long o = ((long long)wg * (L + 1) + pos) * 3;
            out[o]     = __ldg(xb + 3 * node)     - cxyz[w * 3];
            out[o + 1] = __ldg(xb + 3 * node + 1) - cxyz[w * 3 + 1];
            out[o + 2] = __ldg(xb + 3 * node + 2) - cxyz[w * 3 + 2];
        }
    }
}

extern "C" void kernel_launch(void* const* d_in, const int* in_sizes, int n_in,
                              void* d_out, int out_size) {
    const float* xyz     = (const float*)d_in[0];
    const int*   nbrs    = (const int*)d_in[1];
    const int*   centers = (const int*)d_in[2];
    const int*   pN      = (const int*)d_in[3];

    const int walks = in_sizes[2];                  // B*G
    const int L = out_size / (walks * 3) - 1;       // seq_len

    cudaFuncSetAttribute(fused_walk_kernel,
                         cudaFuncAttributeMaxDynamicSharedMemorySize, SMEM_BYTES);

    const int blocks = (walks + 31) / 32;
    fused_walk_kernel<<<blocks, THREADS, SMEM_BYTES>>>(
        xyz, nbrs, centers, pN, (float*)d_out, in_sizes[0], walks, L);
}